// round 17
// baseline (speedup 1.0000x reference)
#include <cuda_runtime.h>
#include <stdint.h>

#define BATCH 8
#define NANCH 100000
#define NGT   64
#define NTOK  256
#define TOPK  27
#define NEG_INF -100000000.0f

#define BINS   64
#define NBIN   (BINS * BINS)
#define INVBIN 0.0625f
#define U64MAX 0xFFFFFFFFFFFFFFFFULL
#define CAP    128                   // slots per bin (mean occupancy 24.4, sigma 4.9)

#define BN   (BATCH * NANCH)
#define NGTS (BATCH * NGT)
#define MAXLIST (NGTS * TOPK)        // 13824
#define MC   (4 * TOPK)              // 108 merge candidates

// ---------------- device scratch ----------------
__device__ int                g_hist [BATCH * NBIN];       // fill cursor -> final count
__device__ float4             g_slots[BATCH * NBIN * CAP]; // {cx, cy, idx_bits, pad} (64 MB)
__device__ unsigned long long g_match[BN];                 // packed (iou<<32 | 63-g), 0 = unmatched
__device__ int                g_list [MAXLIST];            // matched-anchor rows (dupes OK)
__device__ int                g_nlist;

// ---------------- chain kernel 0: zero hist + list counter ----------------
__global__ void zero_kernel() {
    int i = blockIdx.x * blockDim.x + threadIdx.x;
    if (i < BATCH * NBIN) g_hist[i] = 0;
    if (i == 0) g_nlist = 0;
}

// ---------------- chain kernel 1: centers -> padded-bin scatter (MLP=2) ----------------
__global__ void prepscatter_kernel(const float* __restrict__ anchors) {
    int base = blockIdx.x * blockDim.x + threadIdx.x;
#pragma unroll
    for (int j = 0; j < 2; j++) {
        int i = base + j * (BN / 2);
        if (i >= BN) continue;
        float4 a = ((const float4*)anchors)[i];
        float cx = (a.x + a.z) * 0.5f;
        float cy = (a.y + a.w) * 0.5f;
        g_match[i] = 0ULL;
        int b  = i / NANCH, n = i % NANCH;
        int bx = min(BINS - 1, max(0, (int)(cx * INVBIN)));
        int by = min(BINS - 1, max(0, (int)(cy * INVBIN)));
        int bin = b * NBIN + by * BINS + bx;
        int ofs = atomicAdd(&g_hist[bin], 1);
        if (ofs < CAP)                              // overflow statistically impossible
            g_slots[(size_t)bin * CAP + ofs] =
                make_float4(cx, cy, __uint_as_float((unsigned)n), 0.0f);
    }
}

// insert p into sorted (ascending) reg array best[0..26]
#define INSERT27(best, p)                                               \
    {                                                                   \
        _Pragma("unroll")                                               \
        for (int k = TOPK - 1; k >= 0; --k) {                           \
            if (k == 0 || (p) >= best[k - 1]) { best[k] = (p); break; } \
            best[k] = best[k - 1];                                      \
        }                                                               \
    }

// ---------------- chain kernel 2: per-gt top-27 (4 warps) + IoU + scatter + list ----------------
__global__ __launch_bounds__(128) void gt_kernel(const float* __restrict__ anchors,
                                                 const float* __restrict__ gts) {
    const int bg   = blockIdx.x;
    const int b    = bg / NGT;
    const int t    = threadIdx.x;
    const int lane = t & 31;
    const int warp = t >> 5;

    const float4 gt = ((const float4*)gts)[bg];
    const float gcx = (gt.x + gt.z) * 0.5f;
    const float gcy = (gt.y + gt.w) * 0.5f;

    const int* __restrict__ hist = g_hist + b * NBIN;

    __shared__ unsigned long long swk[4][TOPK];   // per-warp top-27
    __shared__ int   stot[4];
    __shared__ unsigned long long skey[TOPK];
    __shared__ int   stotal;
    __shared__ float siou[TOPK];
    __shared__ int   sing[TOPK];
    __shared__ float sthr;

    float W = 16.0f;
    for (;;) {
        int bx0 = max(0, (int)((gcx - W) * INVBIN));
        int bx1 = min(BINS - 1, (int)((gcx + W) * INVBIN));
        int by0 = max(0, (int)((gcy - W) * INVBIN));
        int by1 = min(BINS - 1, (int)((gcy + W) * INVBIN));
        int nbx = bx1 - bx0 + 1, nby = by1 - by0 + 1;
        int nbins = nbx * nby;

        int total = 0;
        unsigned long long best[TOPK];
#pragma unroll
        for (int k = 0; k < TOPK; k++) best[k] = U64MAX;

        // 4 warps take bins round-robin
        for (int bi = warp; bi < nbins; bi += 4) {
            int by = by0 + bi / nbx;
            int bx = bx0 + bi % nbx;
            int bin = by * BINS + bx;
            int cnt = min(hist[bin], CAP);
            total += cnt;
            const float4* __restrict__ slot =
                g_slots + (size_t)(b * NBIN + bin) * CAP;
            for (int i = lane; i < cnt; i += 32) {
                float4 v = slot[i];                // coords embedded
                float dx = v.x - gcx, dy = v.y - gcy;
                float d2 = dx * dx + dy * dy;
                // integer-domain filter (sentinel 0xFFFFFFFF is NaN as float)
                if (__float_as_uint(d2) <= (unsigned)(best[TOPK - 1] >> 32)) {
                    unsigned long long pk =
                        (((unsigned long long)__float_as_uint(d2)) << 32) |
                        __float_as_uint(v.z);
                    if (pk < best[TOPK - 1]) INSERT27(best, pk);
                }
            }
        }

        // per-warp merge: 27 rounds of head-min
        int head = 0;
        for (int r = 0; r < TOPK; r++) {
            unsigned long long c = (head < TOPK) ? best[head] : U64MAX;
            unsigned long long m = c;
#pragma unroll
            for (int s = 16; s > 0; s >>= 1) {
                unsigned long long o = __shfl_xor_sync(0xFFFFFFFFu, m, s);
                if (o < m) m = o;
            }
            if (lane == 0) swk[warp][r] = m;
            if (c == m) head++;
        }
        if (lane == 0) stot[warp] = total;
        if (t < TOPK) skey[t] = U64MAX;            // safe default for short windows
        __syncthreads();

        // cross-warp merge: rank-count over 108 candidates (keys unique;
        // sentinel dupes rank >= #real so ranks 0..26 get the true winners)
        if (t < MC) {
            unsigned long long mine = swk[t / TOPK][t % TOPK];
            if (mine != U64MAX) {
                int rank = 0;
                for (int j = 0; j < MC; j++)
                    rank += (swk[j / TOPK][j % TOPK] < mine);
                if (rank < TOPK) skey[rank] = mine;
            }
        }
        if (t == 0) stotal = stot[0] + stot[1] + stot[2] + stot[3];
        __syncthreads();

        bool full_canvas = (bx0 == 0 && bx1 == BINS - 1 && by0 == 0 && by1 == BINS - 1);
        float d27sq = __uint_as_float((unsigned)(skey[TOPK - 1] >> 32));
        // NaN-safe: when skey[26] is sentinel, d27sq is NaN -> compare false -> expand
        if ((stotal >= TOPK && d27sq < W * W * 0.999f) || full_canvas) break;
        W *= 2.0f;
        __syncthreads();
    }

    // IoU + center-inside for the 27 winners
    if (t < TOPK) {
        int n = (int)(skey[t] & 0xFFFFFFFFu);
        float4 a = ((const float4*)anchors)[b * NANCH + n];
        float area_a = (a.z - a.x) * (a.w - a.y);
        float area_g = (gt.z - gt.x) * (gt.w - gt.y);
        float lx = fmaxf(a.x, gt.x), ly = fmaxf(a.y, gt.y);
        float rx = fminf(a.z, gt.z), ry = fminf(a.w, gt.w);
        float w = fmaxf(rx - lx, 0.0f), h = fmaxf(ry - ly, 0.0f);
        float inter = w * h;
        float uni = area_a + area_g - inter;
        siou[t] = __fdiv_rn(inter, uni);

        float acx = (a.x + a.z) * 0.5f, acy = (a.y + a.w) * 0.5f;
        float l  = acx - gt.x;
        float tp = acy - gt.y;
        float rr = gt.z - acx;
        float bb = gt.w - acy;
        float mn = fminf(fminf(l, tp), fminf(rr, bb));
        sing[t] = (mn > 0.01f) ? 1 : 0;
    }
    __syncthreads();

    if (t == 0) {
        double s = 0.0, ss = 0.0;
        for (int k = 0; k < TOPK; k++) {
            double v = (double)siou[k];
            s += v; ss += v * v;
        }
        double mean = s / TOPK;
        double var  = (ss - s * s / TOPK) / (TOPK - 1);   // ddof=1 (unbiased)
        if (var < 0.0) var = 0.0;
        sthr = (float)(mean + sqrt(var));
    }
    __syncthreads();

    if (t < TOPK) {
        float iou = siou[t];
        if (iou >= sthr && sing[t]) {
            int n = (int)(skey[t] & 0xFFFFFFFFu);
            int g = bg % NGT;
            unsigned long long p =
                (((unsigned long long)__float_as_uint(iou)) << 32) |
                (unsigned)(NGT - 1 - g);
            atomicMax(&g_match[b * NANCH + n], p);
            int li = atomicAdd(&g_nlist, 1);
            g_list[li] = b * NANCH + n;            // dupes OK: same final winner data
        }
    }
}

// ---------------- chain kernel 3: scalars (values / indices / matched_gts) ----------------
__global__ void scalars_kernel(const float* __restrict__ gts, float* __restrict__ out) {
    int i = blockIdx.x * blockDim.x + threadIdx.x;
    if (i >= BN) return;
    int b = i / NANCH;
    unsigned long long m = g_match[i];
    float val; int g;
    if (m) {
        g   = NGT - 1 - (int)(m & 0xFFFFFFFFu);
        val = __uint_as_float((unsigned)(m >> 32));
    } else {
        g = 0; val = NEG_INF;               // argmax of all -INF row is 0
    }
    out[i]      = val;
    out[BN + i] = (float)g;
    float4 gtb = ((const float4*)gts)[b * NGT + g];
    ((float4*)(out + 2 * (size_t)BN))[i] = gtb;
}

// ---------------- writer (low-priority branch): unmatched pattern to ALL token rows ----------------
__global__ __launch_bounds__(256) void pattern_kernel(float* __restrict__ out) {
    int warp = (blockIdx.x * blockDim.x + threadIdx.x) >> 5;
    int lane = threadIdx.x & 31;
    if (warp >= BN) return;
    float4* dst = (float4*)(out + (size_t)6 * BN) + (size_t)warp * (NTOK / 4);
    float4 z = make_float4(0.f, 0.f, 0.f, 0.f);
    __stcs(dst + lane, z);
    float4 z2 = z;
    if (lane == 31) z2.w = 1.0f;            // one-hot at token index 255
    __stcs(dst + lane + 32, z2);
}

// ---------------- join kernel: rewrite matched token rows ----------------
__global__ __launch_bounds__(256) void fixup_kernel(const float* __restrict__ tokens,
                                                    float* __restrict__ out) {
    int warp = (blockIdx.x * blockDim.x + threadIdx.x) >> 5;
    int lane = threadIdx.x & 31;
    if (warp >= g_nlist) return;
    int row = g_list[warp];
    unsigned long long m = g_match[row];     // nonzero: had >=1 positive candidate
    int g = NGT - 1 - (int)(m & 0xFFFFFFFFu);
    int b = row / NANCH;
    const float4* src = (const float4*)(tokens + ((size_t)b * NGT + g) * NTOK);
    float4* dst = (float4*)(out + (size_t)6 * BN) + (size_t)row * (NTOK / 4);
    dst[lane]      = __ldg(src + lane);
    dst[lane + 32] = __ldg(src + lane + 32);
}

// ---------------- launch: prioritized fork/join, ALL handles destroyed before return ----------------
extern "C" void kernel_launch(void* const* d_in, const int* in_sizes, int n_in,
                              void* d_out, int out_size) {
    const float* anchors = (const float*)d_in[0];   // [8,100000,4]
    const float* gts     = (const float*)d_in[1];   // [8,64,4]
    const float* tokens  = (const float*)d_in[2];   // [8,64,256]
    float* out = (float*)d_out;

    int prLeast = 0, prGreatest = 0;
    cudaDeviceGetStreamPriorityRange(&prLeast, &prGreatest);

    cudaStream_t sLo = 0, sHi = 0;
    cudaEvent_t evA = 0, evB = 0, evC = 0;
    bool forked =
        (cudaStreamCreateWithPriority(&sLo, cudaStreamNonBlocking, prLeast)    == cudaSuccess) &&
        (cudaStreamCreateWithPriority(&sHi, cudaStreamNonBlocking, prGreatest) == cudaSuccess) &&
        (cudaEventCreateWithFlags(&evA, cudaEventDisableTiming) == cudaSuccess) &&
        (cudaEventCreateWithFlags(&evB, cudaEventDisableTiming) == cudaSuccess) &&
        (cudaEventCreateWithFlags(&evC, cudaEventDisableTiming) == cudaSuccess);

    const int patgrid = (BN * 32 + 255) / 256;      // 100000 blocks, 1 warp per row

    if (forked) {
        cudaEventRecord(evA, 0);                    // fork point on the capture stream
        cudaStreamWaitEvent(sLo, evA, 0);
        cudaStreamWaitEvent(sHi, evA, 0);

        // low-priority branch: bulk pattern writer
        pattern_kernel<<<patgrid, 256, 0, sLo>>>(out);
        cudaEventRecord(evB, sLo);

        // high-priority branch: assignment chain
        zero_kernel<<<(BATCH * NBIN + 255) / 256, 256, 0, sHi>>>();
        prepscatter_kernel<<<(BN / 2 + 255) / 256, 256, 0, sHi>>>(anchors);
        gt_kernel<<<NGTS, 128, 0, sHi>>>(anchors, gts);
        scalars_kernel<<<(BN + 255) / 256, 256, 0, sHi>>>(gts, out);
        cudaEventRecord(evC, sHi);

        // join both branches back onto the capture stream (side streams exit capture here)
        cudaStreamWaitEvent(0, evB, 0);
        cudaStreamWaitEvent(0, evC, 0);
    } else {
        // sequential fallback (still correct)
        pattern_kernel<<<patgrid, 256>>>(out);
        zero_kernel<<<(BATCH * NBIN + 255) / 256, 256>>>();
        prepscatter_kernel<<<(BN / 2 + 255) / 256, 256>>>(anchors);
        gt_kernel<<<NGTS, 128>>>(anchors, gts);
        scalars_kernel<<<(BN + 255) / 256, 256>>>(gts, out);
    }

    fixup_kernel<<<(MAXLIST * 32 + 255) / 256, 256>>>(tokens, out);

    // destroy everything we created: handles are not part of the captured graph,
    // and after the joins the side streams are no longer in capture mode.
    if (evA) cudaEventDestroy(evA);
    if (evB) cudaEventDestroy(evB);
    if (evC) cudaEventDestroy(evC);
    if (sLo) cudaStreamDestroy(sLo);
    if (sHi) cudaStreamDestroy(sHi);
}